// round 16
// baseline (speedup 1.0000x reference)
#include <cuda_runtime.h>
#include <cstdint>

// Shapes fixed by the problem's setup_inputs.
#define B_      16
#define N_      1024
#define M_      1024
#define CIN_    7
#define C_      8
#define COUT_   16
#define TM_     128     // m-rows per block
#define THREADS_ 1024   // 32 warps: 8 m-subtiles x 4 K-quarters
#define NSTEP_  16      // k16-steps per K-quarter (256 n's)
#define EPS_    1e-8f

typedef unsigned long long ull;
typedef unsigned int u32;

// ---------------- smem layout (static, ~41.5KB) ----------------
//   [0,     8192)  sxq:   512 x {x0,x1 | q0,q1} (n-pairs)
//   [8192, 40960)  bfrag: 64 steps x 32 lanes x uint4 {bh0,bh1,bl0,bl1}
//   [40960,41472)  sw (128 floats); [41472,41536) sb (16 floats)
//   aliases after mainloop:
//   [0,     2048)  dens: 4 K-quarters x 128 m (f32 exact densities)
//   [4096,  8192)  dsc:  final agg [128 m][8 c] f32
//   [8192, 20480)  kred: 24 warps x 32 lanes x float4 (reuses bfrag)
#define OFF_SXQ  0
#define OFF_BF   8192
#define OFF_SW   40960
#define OFF_SB   41472
#define SMEM_BYTES 41536
#define OFF_DENS 0
#define OFF_DSC  4096
#define OFF_KRED 8192

// ---------------- helpers ----------------
__device__ __forceinline__ float ex2f(float v) {
    float r; asm("ex2.approx.f32 %0, %1;" : "=f"(r) : "f"(v)); return r;
}
__device__ __forceinline__ ull pack2(float lo, float hi) {
    ull r; asm("mov.b64 %0, {%1, %2};" : "=l"(r) : "f"(lo), "f"(hi)); return r;
}
__device__ __forceinline__ void unpack2(ull v, float& lo, float& hi) {
    asm("mov.b64 {%0, %1}, %2;" : "=f"(lo), "=f"(hi) : "l"(v));
}
__device__ __forceinline__ ull fma2(ull a, ull b, ull c) {
    ull d; asm("fma.rn.f32x2 %0, %1, %2, %3;" : "=l"(d) : "l"(a), "l"(b), "l"(c));
    return d;
}
__device__ __forceinline__ ull add2(ull a, ull b) {
    ull d; asm("add.rn.f32x2 %0, %1, %2;" : "=l"(d) : "l"(a), "l"(b));
    return d;
}
// pack two f32 into bf16x2: 'lo' -> bits[15:0], 'hi' -> bits[31:16]
__device__ __forceinline__ u32 cvt_bf16x2(float lo, float hi) {
    u32 r; asm("cvt.rn.bf16x2.f32 %0, %1, %2;" : "=r"(r) : "f"(hi), "f"(lo));
    return r;
}
// residual frag: given f32 pair (e0,e1) and their bf16x2 'hi' reg, build lo reg
__device__ __forceinline__ u32 lo_frag(float e0, float e1, u32 hi) {
    float h0 = __uint_as_float(hi << 16);
    float h1 = __uint_as_float(hi & 0xFFFF0000u);
    return cvt_bf16x2(e0 - h0, e1 - h1);
}
// warp-level bf16 MMA: D(16x8,f32) += A(16x16) * B(16x8)
__device__ __forceinline__ void mma_bf16(float& d0, float& d1, float& d2, float& d3,
                                         u32 a0, u32 a1, u32 a2, u32 a3,
                                         u32 b0, u32 b1) {
    asm volatile(
        "mma.sync.aligned.m16n8k16.row.col.f32.bf16.bf16.f32 "
        "{%0,%1,%2,%3}, {%4,%5,%6,%7}, {%8,%9}, {%0,%1,%2,%3};"
        : "+f"(d0), "+f"(d1), "+f"(d2), "+f"(d3)
        : "r"(a0), "r"(a1), "r"(a2), "r"(a3), "r"(b0), "r"(b1));
}

// Fused epilogue for one m: feats -> 16 outputs.
__device__ __forceinline__ void epilogue(const float* a, const float* sw,
                                         const float* sb, float* op) {
    float density = a[0];
    float inv = 1.0f / (density + EPS_);
    float feats[C_];
    feats[0] = density;
#pragma unroll
    for (int c = 1; c < C_; c++) feats[c] = a[c] * inv;
#pragma unroll
    for (int og = 0; og < 4; og++) {
        float rr[4];
#pragma unroll
        for (int k = 0; k < 4; k++) {
            const int o = og * 4 + k;
            float sv = sb[o];
#pragma unroll
            for (int c = 0; c < C_; c++)
                sv = fmaf(sw[o * C_ + c], feats[c], sv);
            rr[k] = sv;
        }
        *(float4*)(op + og * 4) = make_float4(rr[0], rr[1], rr[2], rr[3]);
    }
}

__global__ __launch_bounds__(THREADS_, 1)
void convdeepset_kernel(const float* __restrict__ x,     // [B, N]
                        const float* __restrict__ y,     // [B, N, CIN]
                        const float* __restrict__ t,     // [B, M]
                        const float* __restrict__ sigma, // [C]
                        const float* __restrict__ w,     // [COUT, C]
                        const float* __restrict__ bias,  // [COUT]
                        float* __restrict__ out)         // [B, M, COUT]
{
    __shared__ __align__(16) char smem_raw[SMEM_BYTES];
    ulonglong2* sxq   = (ulonglong2*)(smem_raw + OFF_SXQ);   // [512]
    uint4*      bfrag = (uint4*)(smem_raw + OFF_BF);         // [64*32]
    float*      sw    = (float*)(smem_raw + OFF_SW);
    float*      sb    = (float*)(smem_raw + OFF_SB);

    const int b    = blockIdx.y;
    const int m0   = blockIdx.x * TM_;
    const int tid  = threadIdx.x;
    const int wrp  = tid >> 5;
    const int lane = tid & 31;
    const int g    = lane >> 2;   // fragment group row / B column (channel)
    const int tt   = lane & 3;    // fragment k-pair selector

    if (tid < COUT_ * C_)                sw[tid] = w[tid];
    if (tid >= 128 && tid < 128 + COUT_) sb[tid - 128] = bias[tid - 128];

    const float LOG2E = 1.4426950408889634f;
    const float s0  = expf(sigma[0]);
    const float k20 = -(0.5f * LOG2E) / (s0 * s0);
    bool uniform = true;
#pragma unroll
    for (int c = 1; c < C_; c++) {
        float s = expf(sigma[c]);
        uniform &= ((-(0.5f * LOG2E) / (s * s)) == k20);
    }

    const float* xb  = x + b * N_;
    const float* ybp = y + (size_t)b * N_ * CIN_;

    if (uniform) {
        // ---- Stage x-pairs {x0,x1 | q0,q1}, q = k20*x^2 (tid<512) ----
        if (tid < 512) {
            const float2 xv = ((const float2*)xb)[tid];
            sxq[tid] = make_ulonglong2(pack2(xv.x, xv.y),
                                       pack2(k20 * xv.x * xv.x, k20 * xv.y * xv.y));
        }
        // ---- Stage B fragments: uint4 {bh0, bh1, bl0, bl1} per (step, lane) ----
#pragma unroll
        for (int r = 0; r < 2; r++) {
            const int idx = tid + r * THREADS_;
            const int s  = idx >> 5;
            const int ln = idx & 31;
            const int gg = ln >> 2, ttt = ln & 3;
            const int n0 = s * 16 + 2 * ttt;
            float v00, v01, v10, v11;
            if (gg == 0) {
                v00 = v01 = v10 = v11 = 1.0f;
            } else {
                const float* yp = ybp + (size_t)n0 * CIN_ + (gg - 1);
                v00 = yp[0];
                v01 = yp[CIN_];
                v10 = yp[8 * CIN_];
                v11 = yp[9 * CIN_];
            }
            u32 h0 = cvt_bf16x2(v00, v01);
            u32 h1 = cvt_bf16x2(v10, v11);
            bfrag[idx] = make_uint4(h0, h1,
                                    lo_frag(v00, v01, h0), lo_frag(v10, v11, h1));
        }
        __syncthreads();

        // ---- Mainloop: warp (wrp&7) owns 16 m-rows, (wrp>>3) a K-quarter ----
        const int mw = (wrp & 7) * 16;
        const int kq = wrp >> 3;             // 0..3
        const float tm0 = t[b * M_ + m0 + mw + g];
        const float tm1 = t[b * M_ + m0 + mw + g + 8];
        const ull UU0 = pack2(-2.0f * k20 * tm0, -2.0f * k20 * tm0);
        const ull TT0 = pack2(k20 * tm0 * tm0,   k20 * tm0 * tm0);
        const ull UU1 = pack2(-2.0f * k20 * tm1, -2.0f * k20 * tm1);
        const ull TT1 = pack2(k20 * tm1 * tm1,   k20 * tm1 * tm1);

        // Two independent accumulator chains + exact f32 density.
        float p0 = 0.0f, p1 = 0.0f, p2 = 0.0f, p3 = 0.0f;   // Ahi*Bhi
        float q0 = 0.0f, q1 = 0.0f, q2 = 0.0f, q3 = 0.0f;   // Ahi*Blo
        float dA = 0.0f, dB = 0.0f;                         // density rows g, g+8

        const ulonglong2* xptr = sxq + kq * (NSTEP_ * 8) + tt;
        const uint4*      bptr = bfrag + kq * (NSTEP_ * 32) + lane;

#pragma unroll 4
        for (int sl = 0; sl < NSTEP_; sl++) {
            const ulonglong2 v0 = xptr[0];
            const ulonglong2 v1 = xptr[4];
            xptr += 8;
            const uint4 bf = bptr[0];
            bptr += 32;
            // exponent args (packed): arg = U*x + T + q
            ull ga0 = add2(fma2(UU0, v0.x, TT0), v0.y);
            ull ga1 = add2(fma2(UU1, v0.x, TT1), v0.y);
            ull ga2 = add2(fma2(UU0, v1.x, TT0), v1.y);
            ull ga3 = add2(fma2(UU1, v1.x, TT1), v1.y);
            float e00, e01, e10, e11, e20, e21, e30, e31;
            unpack2(ga0, e00, e01);
            unpack2(ga1, e10, e11);
            unpack2(ga2, e20, e21);
            unpack2(ga3, e30, e31);
            e00 = ex2f(e00); e01 = ex2f(e01);
            e10 = ex2f(e10); e11 = ex2f(e11);
            e20 = ex2f(e20); e21 = ex2f(e21);
            e30 = ex2f(e30); e31 = ex2f(e31);
            // exact density on the fma pipe (row g and row g+8)
            dA += (e00 + e01) + (e20 + e21);
            dB += (e10 + e11) + (e30 + e31);
            // A fragments (hi only)
            u32 ah0 = cvt_bf16x2(e00, e01);
            u32 ah1 = cvt_bf16x2(e10, e11);
            u32 ah2 = cvt_bf16x2(e20, e21);
            u32 ah3 = cvt_bf16x2(e30, e31);
            // chain P: Ahi*Bhi ; chain Q: Ahi*Blo
            mma_bf16(p0, p1, p2, p3, ah0, ah1, ah2, ah3, bf.x, bf.y);
            mma_bf16(q0, q1, q2, q3, ah0, ah1, ah2, ah3, bf.z, bf.w);
        }
        float d0 = p0 + q0, d1 = p1 + q1, d2 = p2 + q2, d3 = p3 + q3;
        // in-warp density reduction over the 4 tt-lanes sharing each row
        dA += __shfl_xor_sync(0xffffffffu, dA, 1);
        dA += __shfl_xor_sync(0xffffffffu, dA, 2);
        dB += __shfl_xor_sync(0xffffffffu, dB, 1);
        dB += __shfl_xor_sync(0xffffffffu, dB, 2);

        // ---- Reduce the 4 K-quarters (kred aliases dead bfrag) ----
        __syncthreads();
        float* dens = (float*)(smem_raw + OFF_DENS);
        if (tt == 0) {
            dens[kq * 128 + mw + g]     = dA;
            dens[kq * 128 + mw + g + 8] = dB;
        }
        float4* kred = (float4*)(smem_raw + OFF_KRED);
        if (kq > 0)
            kred[((kq - 1) * 8 + (wrp & 7)) * 32 + lane] =
                make_float4(d0, d1, d2, d3);
        __syncthreads();
        float* dsc = (float*)(smem_raw + OFF_DSC);
        if (kq == 0) {
#pragma unroll
            for (int p = 0; p < 3; p++) {
                const float4 r = kred[(p * 8 + (wrp & 7)) * 32 + lane];
                d0 += r.x; d1 += r.y; d2 += r.z; d3 += r.w;
            }
            // D layout: lane holds D[g][2t], D[g][2t+1], D[g+8][2t], D[g+8][2t+1]
            const int ml = mw + g;
            *(float2*)(dsc + ml * C_ + 2 * tt)       = make_float2(d0, d1);
            *(float2*)(dsc + (ml + 8) * C_ + 2 * tt) = make_float2(d2, d3);
        }
        __syncthreads();

        // ---- Fused epilogue: threads 0..127, one m each ----
        if (tid < TM_) {
            float a[C_];
            float4 r0 = *(float4*)(dsc + tid * C_);
            float4 r1 = *(float4*)(dsc + tid * C_ + 4);
            // channel 0 (density) comes from the exact f32 accumulation
            a[0] = dens[tid] + dens[128 + tid] + dens[256 + tid] + dens[384 + tid];
            a[1] = r0.y; a[2] = r0.z; a[3] = r0.w;
            a[4] = r1.x; a[5] = r1.y; a[6] = r1.z; a[7] = r1.w;
            epilogue(a, sw, sb, out + ((size_t)(b * M_ + m0 + tid)) * COUT_);
        }
    } else {
        // ============ general-sigma fallback (correct, cold) ============
        float k2[C_];
#pragma unroll
        for (int c = 0; c < C_; c++) {
            float s = expf(sigma[c]);
            k2[c] = -(0.5f * LOG2E) / (s * s);
        }
        __syncthreads();
        if (tid < TM_) {
            const int m = m0 + tid;
            const float tmv = t[b * M_ + m];
            float a[C_];
#pragma unroll
            for (int c = 0; c < C_; c++) a[c] = 0.0f;
            for (int n = 0; n < N_; n++) {
                const float dd = xb[n] - tmv;
                const float dd2 = dd * dd;
                const float* yp = ybp + (size_t)n * CIN_;
                a[0] += ex2f(k2[0] * dd2);
#pragma unroll
                for (int c = 1; c < C_; c++)
                    a[c] += yp[c - 1] * ex2f(k2[c] * dd2);
            }
            epilogue(a, sw, sb, out + ((size_t)(b * M_ + m)) * COUT_);
        }
    }
}

extern "C" void kernel_launch(void* const* d_in, const int* in_sizes, int n_in,
                              void* d_out, int out_size) {
    (void)in_sizes; (void)n_in; (void)out_size;
    const float* x     = (const float*)d_in[0];
    const float* y     = (const float*)d_in[1];
    const float* t     = (const float*)d_in[2];
    const float* sigma = (const float*)d_in[3];
    const float* w     = (const float*)d_in[4];
    const float* bias  = (const float*)d_in[5];
    float* out = (float*)d_out;

    dim3 grid(M_ / TM_, B_);
    convdeepset_kernel<<<grid, THREADS_>>>(x, y, t, sigma, w, bias, out);
}

// round 17
// speedup vs baseline: 1.1191x; 1.1191x over previous
#include <cuda_runtime.h>
#include <cstdint>

// Shapes fixed by the problem's setup_inputs.
#define B_      16
#define N_      1024
#define M_      1024
#define CIN_    7
#define C_      8
#define COUT_   16
#define TM_     128     // m-rows per block
#define THREADS_ 1024   // 32 warps: 8 m-subtiles x 4 K-quarters
#define NSTEP_  16      // k16-steps per K-quarter (256 n's)
#define EPS_    1e-8f

typedef unsigned long long ull;
typedef unsigned int u32;

// ---------------- smem layout (static, ~25.2KB) ----------------
//   [0,     8192)  sxq:   512 x {x0,x1 | q0,q1} (n-pairs)
//   [8192, 24576)  bfrag: 64 steps x 32 lanes x uint2 {bh0,bh1} (f16x2)
//   [24576,25088)  sw (128 floats); [25088,25152) sb (16 floats)
//   aliases after mainloop (sxq/bfrag dead):
//   [0,    12288)  kred: 24 warps x 32 lanes x float4
//   [12288,16384)  dsc:  final agg [128 m][8 c] f32
#define OFF_SXQ  0
#define OFF_BF   8192
#define OFF_SW   24576
#define OFF_SB   25088
#define SMEM_BYTES 25152
#define OFF_KRED 0
#define OFF_DSC  12288

// ---------------- helpers ----------------
__device__ __forceinline__ float ex2f(float v) {
    float r; asm("ex2.approx.f32 %0, %1;" : "=f"(r) : "f"(v)); return r;
}
__device__ __forceinline__ ull pack2(float lo, float hi) {
    ull r; asm("mov.b64 %0, {%1, %2};" : "=l"(r) : "f"(lo), "f"(hi)); return r;
}
__device__ __forceinline__ void unpack2(ull v, float& lo, float& hi) {
    asm("mov.b64 {%0, %1}, %2;" : "=f"(lo), "=f"(hi) : "l"(v));
}
__device__ __forceinline__ ull fma2(ull a, ull b, ull c) {
    ull d; asm("fma.rn.f32x2 %0, %1, %2, %3;" : "=l"(d) : "l"(a), "l"(b), "l"(c));
    return d;
}
__device__ __forceinline__ ull add2(ull a, ull b) {
    ull d; asm("add.rn.f32x2 %0, %1, %2;" : "=l"(d) : "l"(a), "l"(b));
    return d;
}
// pack two f32 into f16x2: 'lo' -> bits[15:0], 'hi' -> bits[31:16]
__device__ __forceinline__ u32 cvt_f16x2(float lo, float hi) {
    u32 r; asm("cvt.rn.f16x2.f32 %0, %1, %2;" : "=r"(r) : "f"(hi), "f"(lo));
    return r;
}
// warp-level f16 MMA: D(16x8,f32) += A(16x16,f16) * B(16x8,f16)
__device__ __forceinline__ void mma_f16(float& d0, float& d1, float& d2, float& d3,
                                        u32 a0, u32 a1, u32 a2, u32 a3,
                                        u32 b0, u32 b1) {
    asm volatile(
        "mma.sync.aligned.m16n8k16.row.col.f32.f16.f16.f32 "
        "{%0,%1,%2,%3}, {%4,%5,%6,%7}, {%8,%9}, {%0,%1,%2,%3};"
        : "+f"(d0), "+f"(d1), "+f"(d2), "+f"(d3)
        : "r"(a0), "r"(a1), "r"(a2), "r"(a3), "r"(b0), "r"(b1));
}

// Fused epilogue for one m: agg -> 16 outputs.
__device__ __forceinline__ void epilogue(const float* a, const float* sw,
                                         const float* sb, float* op) {
    float density = a[0];
    float inv = 1.0f / (density + EPS_);
    float feats[C_];
    feats[0] = density;
#pragma unroll
    for (int c = 1; c < C_; c++) feats[c] = a[c] * inv;
#pragma unroll
    for (int og = 0; og < 4; og++) {
        float rr[4];
#pragma unroll
        for (int k = 0; k < 4; k++) {
            const int o = og * 4 + k;
            float sv = sb[o];
#pragma unroll
            for (int c = 0; c < C_; c++)
                sv = fmaf(sw[o * C_ + c], feats[c], sv);
            rr[k] = sv;
        }
        *(float4*)(op + og * 4) = make_float4(rr[0], rr[1], rr[2], rr[3]);
    }
}

__global__ __launch_bounds__(THREADS_, 1)
void convdeepset_kernel(const float* __restrict__ x,     // [B, N]
                        const float* __restrict__ y,     // [B, N, CIN]
                        const float* __restrict__ t,     // [B, M]
                        const float* __restrict__ sigma, // [C]
                        const float* __restrict__ w,     // [COUT, C]
                        const float* __restrict__ bias,  // [COUT]
                        float* __restrict__ out)         // [B, M, COUT]
{
    __shared__ __align__(16) char smem_raw[SMEM_BYTES];
    ulonglong2* sxq   = (ulonglong2*)(smem_raw + OFF_SXQ);   // [512]
    uint2*      bfrag = (uint2*)(smem_raw + OFF_BF);         // [64*32]
    float*      sw    = (float*)(smem_raw + OFF_SW);
    float*      sb    = (float*)(smem_raw + OFF_SB);

    const int b    = blockIdx.y;
    const int m0   = blockIdx.x * TM_;
    const int tid  = threadIdx.x;
    const int wrp  = tid >> 5;
    const int lane = tid & 31;
    const int g    = lane >> 2;   // fragment group row / B column (channel)
    const int tt   = lane & 3;    // fragment k-pair selector

    if (tid < COUT_ * C_)                sw[tid] = w[tid];
    if (tid >= 128 && tid < 128 + COUT_) sb[tid - 128] = bias[tid - 128];

    const float LOG2E = 1.4426950408889634f;
    const float s0  = expf(sigma[0]);
    const float k20 = -(0.5f * LOG2E) / (s0 * s0);
    bool uniform = true;
#pragma unroll
    for (int c = 1; c < C_; c++) {
        float s = expf(sigma[c]);
        uniform &= ((-(0.5f * LOG2E) / (s * s)) == k20);
    }

    const float* xb  = x + b * N_;
    const float* ybp = y + (size_t)b * N_ * CIN_;

    if (uniform) {
        // ---- Stage x-pairs {x0,x1 | q0,q1}, q = k20*x^2 (tid<512) ----
        if (tid < 512) {
            const float2 xv = ((const float2*)xb)[tid];
            sxq[tid] = make_ulonglong2(pack2(xv.x, xv.y),
                                       pack2(k20 * xv.x * xv.x, k20 * xv.y * xv.y));
        }
        // ---- Stage B fragments: uint2 {bh0, bh1} (f16x2) per (step, lane) ----
        // bh0 = {Ycat[16s+2t][g], Ycat[16s+2t+1][g]},
        // bh1 = {Ycat[16s+2t+8][g], Ycat[16s+2t+9][g]}
#pragma unroll
        for (int r = 0; r < 2; r++) {
            const int idx = tid + r * THREADS_;
            const int s  = idx >> 5;
            const int ln = idx & 31;
            const int gg = ln >> 2, ttt = ln & 3;
            const int n0 = s * 16 + 2 * ttt;
            float v00, v01, v10, v11;
            if (gg == 0) {
                v00 = v01 = v10 = v11 = 1.0f;
            } else {
                const float* yp = ybp + (size_t)n0 * CIN_ + (gg - 1);
                v00 = yp[0];
                v01 = yp[CIN_];
                v10 = yp[8 * CIN_];
                v11 = yp[9 * CIN_];
            }
            bfrag[idx] = make_uint2(cvt_f16x2(v00, v01), cvt_f16x2(v10, v11));
        }
        __syncthreads();

        // ---- Mainloop: warp (wrp&7) owns 16 m-rows, (wrp>>3) a K-quarter ----
        const int mw = (wrp & 7) * 16;
        const int kq = wrp >> 3;             // 0..3
        const float tm0 = t[b * M_ + m0 + mw + g];
        const float tm1 = t[b * M_ + m0 + mw + g + 8];
        const ull UU0 = pack2(-2.0f * k20 * tm0, -2.0f * k20 * tm0);
        const ull TT0 = pack2(k20 * tm0 * tm0,   k20 * tm0 * tm0);
        const ull UU1 = pack2(-2.0f * k20 * tm1, -2.0f * k20 * tm1);
        const ull TT1 = pack2(k20 * tm1 * tm1,   k20 * tm1 * tm1);

        float d0 = 0.0f, d1 = 0.0f, d2 = 0.0f, d3 = 0.0f;

        const ulonglong2* xptr = sxq + kq * (NSTEP_ * 8) + tt;
        const uint2*      bptr = bfrag + kq * (NSTEP_ * 32) + lane;

#pragma unroll 4
        for (int sl = 0; sl < NSTEP_; sl++) {
            const ulonglong2 v0 = xptr[0];
            const ulonglong2 v1 = xptr[4];
            xptr += 8;
            const uint2 bf = bptr[0];
            bptr += 32;
            // exponent args (packed): arg = U*x + T + q
            ull ga0 = add2(fma2(UU0, v0.x, TT0), v0.y);
            ull ga1 = add2(fma2(UU1, v0.x, TT1), v0.y);
            ull ga2 = add2(fma2(UU0, v1.x, TT0), v1.y);
            ull ga3 = add2(fma2(UU1, v1.x, TT1), v1.y);
            float e00, e01, e10, e11, e20, e21, e30, e31;
            unpack2(ga0, e00, e01);
            unpack2(ga1, e10, e11);
            unpack2(ga2, e20, e21);
            unpack2(ga3, e30, e31);
            e00 = ex2f(e00); e01 = ex2f(e01);
            e10 = ex2f(e10); e11 = ex2f(e11);
            e20 = ex2f(e20); e21 = ex2f(e21);
            e30 = ex2f(e30); e31 = ex2f(e31);
            // A fragments (f16x2) -- single pass, no residuals
            u32 ah0 = cvt_f16x2(e00, e01);
            u32 ah1 = cvt_f16x2(e10, e11);
            u32 ah2 = cvt_f16x2(e20, e21);
            u32 ah3 = cvt_f16x2(e30, e31);
            mma_f16(d0, d1, d2, d3, ah0, ah1, ah2, ah3, bf.x, bf.y);
        }

        // ---- Reduce the 4 K-quarters (kred aliases dead sxq/bfrag) ----
        __syncthreads();
        float4* kred = (float4*)(smem_raw + OFF_KRED);
        if (kq > 0)
            kred[((kq - 1) * 8 + (wrp & 7)) * 32 + lane] =
                make_float4(d0, d1, d2, d3);
        __syncthreads();
        float* dsc = (float*)(smem_raw + OFF_DSC);
        if (kq == 0) {
#pragma unroll
            for (int p = 0; p < 3; p++) {
                const float4 r = kred[(p * 8 + (wrp & 7)) * 32 + lane];
                d0 += r.x; d1 += r.y; d2 += r.z; d3 += r.w;
            }
            // D layout: lane holds D[g][2t], D[g][2t+1], D[g+8][2t], D[g+8][2t+1]
            const int ml = mw + g;
            *(float2*)(dsc + ml * C_ + 2 * tt)       = make_float2(d0, d1);
            *(float2*)(dsc + (ml + 8) * C_ + 2 * tt) = make_float2(d2, d3);
        }
        __syncthreads();

        // ---- Fused epilogue: threads 0..127, one m each ----
        if (tid < TM_) {
            float a[C_];
            float4 r0 = *(float4*)(dsc + tid * C_);
            float4 r1 = *(float4*)(dsc + tid * C_ + 4);
            a[0] = r0.x; a[1] = r0.y; a[2] = r0.z; a[3] = r0.w;
            a[4] = r1.x; a[5] = r1.y; a[6] = r1.z; a[7] = r1.w;
            epilogue(a, sw, sb, out + ((size_t)(b * M_ + m0 + tid)) * COUT_);
        }
    } else {
        // ============ general-sigma fallback (correct, cold) ============
        float k2[C_];
#pragma unroll
        for (int c = 0; c < C_; c++) {
            float s = expf(sigma[c]);
            k2[c] = -(0.5f * LOG2E) / (s * s);
        }
        __syncthreads();
        if (tid < TM_) {
            const int m = m0 + tid;
            const float tmv = t[b * M_ + m];
            float a[C_];
#pragma unroll
            for (int c = 0; c < C_; c++) a[c] = 0.0f;
            for (int n = 0; n < N_; n++) {
                const float dd = xb[n] - tmv;
                const float dd2 = dd * dd;
                const float* yp = ybp + (size_t)n * CIN_;
                a[0] += ex2f(k2[0] * dd2);
#pragma unroll
                for (int c = 1; c < C_; c++)
                    a[c] += yp[c - 1] * ex2f(k2[c] * dd2);
            }
            epilogue(a, sw, sb, out + ((size_t)(b * M_ + m)) * COUT_);
        }
    }
}

extern "C" void kernel_launch(void* const* d_in, const int* in_sizes, int n_in,
                              void* d_out, int out_size) {
    (void)in_sizes; (void)n_in; (void)out_size;
    const float* x     = (const float*)d_in[0];
    const float* y     = (const float*)d_in[1];
    const float* t     = (const float*)d_in[2];
    const float* sigma = (const float*)d_in[3];
    const float* w     = (const float*)d_in[4];
    const float* bias  = (const float*)d_in[5];
    float* out = (float*)d_out;

    dim3 grid(M_ / TM_, B_);
    convdeepset_kernel<<<grid, THREADS_>>>(x, y, t, sigma, w, bias, out);
}